// round 4
// baseline (speedup 1.0000x reference)
#include <cuda_runtime.h>

#define NN 50000
#define NE 800000
#define HID 128
#define H4  32
#define SLOPE 0.2f
#define FULL 0xffffffffu

// ---------------- scratch ----------------
__device__ float g_xp[NN * HID];     // GEMM output (xp / z)
__device__ float g_cur[NN * HID];    // current activation
__device__ float g_ssrc[NN];
__device__ float g_sdst[NN];
__device__ float g_deg[NN];
__device__ float g_dinv[NN];
__device__ int   g_cnt[NN];
__device__ int   g_rowptr[NN + 1];
__device__ int   g_cursor[NN];
__device__ int   g_csrc[NE];         // CSR-sorted source ids
__device__ float g_cw[NE];           // CSR-sorted GCN coefficients

// ---------------- f32x2 helpers ----------------
__device__ __forceinline__ unsigned long long pk2(float a) {
    unsigned long long r;
    asm("mov.b64 %0, {%1,%1};" : "=l"(r) : "f"(a));
    return r;
}
__device__ __forceinline__ void fma2(unsigned long long& d,
                                     unsigned long long a,
                                     unsigned long long b) {
    asm("fma.rn.f32x2 %0, %1, %2, %0;" : "+l"(d) : "l"(a), "l"(b));
}
union U2 { unsigned long long u; float2 f; };

__device__ __forceinline__ float getc(const float4& v, int c) {
    return c == 0 ? v.x : c == 1 ? v.y : c == 2 ? v.z : v.w;
}

// ================= CSR build =================
__global__ void k_zero() {
    int i = blockIdx.x * blockDim.x + threadIdx.x;
    if (i < NN) { g_cnt[i] = 0; g_deg[i] = 1.0f; }   // self-loop weight
}
__global__ void k_hist(const int* __restrict__ ei, const float* __restrict__ w) {
    int e = blockIdx.x * blockDim.x + threadIdx.x;
    if (e < NE) {
        int d = ei[NE + e];
        atomicAdd(&g_cnt[d], 1);
        atomicAdd(&g_deg[d], w[e]);
    }
}
#define SCAN_T 1024
__global__ void k_scan() {
    __shared__ int sh[SCAN_T];
    int t = threadIdx.x;
    const int chunk = (NN + SCAN_T - 1) / SCAN_T;
    int beg = t * chunk, end = min(beg + chunk, NN);
    int s = 0;
    for (int i = beg; i < end; i++) {
        s += g_cnt[i];
        g_dinv[i] = rsqrtf(g_deg[i]);
    }
    sh[t] = s;
    __syncthreads();
    for (int o = 1; o < SCAN_T; o <<= 1) {
        int v = (t >= o) ? sh[t - o] : 0;
        __syncthreads();
        sh[t] += v;
        __syncthreads();
    }
    int run = (t == 0) ? 0 : sh[t - 1];
    for (int i = beg; i < end; i++) {
        int c = g_cnt[i];
        g_rowptr[i] = run;
        g_cursor[i] = run;
        run += c;
    }
    if (t == SCAN_T - 1) g_rowptr[NN] = run;
}
__global__ void k_place(const int* __restrict__ ei, const float* __restrict__ w) {
    int e = blockIdx.x * blockDim.x + threadIdx.x;
    if (e >= NE) return;
    int s = ei[e], d = ei[NE + e];
    int pos = atomicAdd(&g_cursor[d], 1);
    g_csrc[pos] = s;
    g_cw[pos] = g_dinv[s] * w[e] * g_dinv[d];   // precomputed GCN coefficient
}

// ================= GEMM: 8 rows/warp, f32x2 =================
// g_xp[r,:] = A[r,:] @ W ; A==nullptr means read g_cur (device symbol).
template <bool GAT>
__global__ void k_gemm(const float* __restrict__ A, const float* __restrict__ W,
                       const float* __restrict__ a_src, const float* __restrict__ a_dst) {
    int gw = (blockIdx.x * blockDim.x + threadIdx.x) >> 5;
    int lane = threadIdx.x & 31;
    int r0 = gw * 8;
    if (r0 >= NN) return;
    const float* Ap = A ? A : g_cur;
    const float4* A4 = reinterpret_cast<const float4*>(Ap);
    const ulonglong2* W2 = reinterpret_cast<const ulonglong2*>(W);

    unsigned long long accA[8], accB[8];
#pragma unroll
    for (int r = 0; r < 8; r++) { accA[r] = 0ull; accB[r] = 0ull; }

#pragma unroll 2
    for (int k4 = 0; k4 < 32; k4++) {
        float4 a[8];
#pragma unroll
        for (int r = 0; r < 8; r++) a[r] = __ldg(A4 + (r0 + r) * H4 + k4);
#pragma unroll
        for (int j = 0; j < 4; j++) {
            ulonglong2 b = __ldg(W2 + (k4 * 4 + j) * H4 + lane);
#pragma unroll
            for (int r = 0; r < 8; r++) {
                unsigned long long t = pk2(getc(a[r], j));
                fma2(accA[r], t, b.x);
                fma2(accB[r], t, b.y);
            }
        }
    }

    float4 as, ad;
    if (GAT) {
        as = __ldg(reinterpret_cast<const float4*>(a_src) + lane);
        ad = __ldg(reinterpret_cast<const float4*>(a_dst) + lane);
    }
#pragma unroll
    for (int i = 0; i < 8; i++) {
        U2 ua, ub;
        ua.u = accA[i]; ub.u = accB[i];
        float4 o = make_float4(ua.f.x, ua.f.y, ub.f.x, ub.f.y);
        reinterpret_cast<float4*>(g_xp)[(r0 + i) * H4 + lane] = o;
        if (GAT) {
            float ps = o.x * as.x + o.y * as.y + o.z * as.z + o.w * as.w;
            float pd = o.x * ad.x + o.y * ad.y + o.z * ad.z + o.w * ad.w;
            for (int of = 16; of; of >>= 1) {
                ps += __shfl_xor_sync(FULL, ps, of);
                pd += __shfl_xor_sync(FULL, pd, of);
            }
            if (lane == 0) {
                g_ssrc[r0 + i] = ps;
                g_sdst[r0 + i] = pd;
            }
        }
    }
}

// ================= GAT gather: single pass (no max-shift) =================
__global__ void k_gat(const float* __restrict__ b_gat, float* __restrict__ out) {
    int gw = (blockIdx.x * blockDim.x + threadIdx.x) >> 5;
    int lane = threadIdx.x & 31;
    if (gw >= NN) return;
    int off = g_rowptr[gw], end = g_rowptr[gw + 1];
    float sdst_d = g_sdst[gw];
    float el = g_ssrc[gw] + sdst_d;
    el = el > 0.f ? el : SLOPE * el;
    float p0 = __expf(el);

    const float4* xp4 = reinterpret_cast<const float4*>(g_xp);
    float4 xd = xp4[gw * H4 + lane];
    float4 acc = make_float4(p0 * xd.x, p0 * xd.y, p0 * xd.z, p0 * xd.w);
    float psum = (lane == 0) ? p0 : 0.0f;

    for (int base = off; base < end; base += 32) {
        int e = base + lane;
        float p = 0.f;
        int s = 0;
        if (e < end) {
            s = g_csrc[e];
            float sc = g_ssrc[s] + sdst_d;
            sc = sc > 0.f ? sc : SLOPE * sc;
            p = __expf(sc);
        }
        psum += p;
        int cnt = min(32, end - base);
        int j = 0;
        for (; j + 4 <= cnt; j += 4) {
            float pj0 = __shfl_sync(FULL, p, j + 0);
            float pj1 = __shfl_sync(FULL, p, j + 1);
            float pj2 = __shfl_sync(FULL, p, j + 2);
            float pj3 = __shfl_sync(FULL, p, j + 3);
            int sj0 = __shfl_sync(FULL, s, j + 0);
            int sj1 = __shfl_sync(FULL, s, j + 1);
            int sj2 = __shfl_sync(FULL, s, j + 2);
            int sj3 = __shfl_sync(FULL, s, j + 3);
            float4 x0 = xp4[sj0 * H4 + lane];
            float4 x1 = xp4[sj1 * H4 + lane];
            float4 x2 = xp4[sj2 * H4 + lane];
            float4 x3 = xp4[sj3 * H4 + lane];
            acc.x += pj0 * x0.x; acc.y += pj0 * x0.y; acc.z += pj0 * x0.z; acc.w += pj0 * x0.w;
            acc.x += pj1 * x1.x; acc.y += pj1 * x1.y; acc.z += pj1 * x1.z; acc.w += pj1 * x1.w;
            acc.x += pj2 * x2.x; acc.y += pj2 * x2.y; acc.z += pj2 * x2.z; acc.w += pj2 * x2.w;
            acc.x += pj3 * x3.x; acc.y += pj3 * x3.y; acc.z += pj3 * x3.z; acc.w += pj3 * x3.w;
        }
        for (; j < cnt; j++) {
            float pj = __shfl_sync(FULL, p, j);
            int sj = __shfl_sync(FULL, s, j);
            float4 xs = xp4[sj * H4 + lane];
            acc.x += pj * xs.x; acc.y += pj * xs.y;
            acc.z += pj * xs.z; acc.w += pj * xs.w;
        }
    }
    for (int o = 16; o; o >>= 1) psum += __shfl_xor_sync(FULL, psum, o);
    float inv = 1.0f / psum;
    float4 b = __ldg(reinterpret_cast<const float4*>(b_gat) + lane);
    float4 h = make_float4(acc.x * inv + b.x, acc.y * inv + b.y,
                           acc.z * inv + b.z, acc.w * inv + b.w);
    reinterpret_cast<float4*>(g_cur)[gw * H4 + lane] = h;
    reinterpret_cast<float4*>(out)[gw * H4 + lane] = h;
}

// ================= GCN gather (precomputed coeffs, MLP-4) =================
__global__ void k_gcn(const float* __restrict__ b_gcn, float* __restrict__ out) {
    int gw = (blockIdx.x * blockDim.x + threadIdx.x) >> 5;
    int lane = threadIdx.x & 31;
    if (gw >= NN) return;
    int off = g_rowptr[gw], end = g_rowptr[gw + 1];
    float dv = g_dinv[gw];
    const float4* z4 = reinterpret_cast<const float4*>(g_xp);
    float cs = dv * dv;
    float4 zd = z4[gw * H4 + lane];
    float4 acc = make_float4(cs * zd.x, cs * zd.y, cs * zd.z, cs * zd.w);

    for (int base = off; base < end; base += 32) {
        int e = base + lane;
        float c = 0.f;
        int s = 0;
        if (e < end) {
            s = g_csrc[e];
            c = g_cw[e];
        }
        int cnt = min(32, end - base);
        int j = 0;
        for (; j + 4 <= cnt; j += 4) {
            float cj0 = __shfl_sync(FULL, c, j + 0);
            float cj1 = __shfl_sync(FULL, c, j + 1);
            float cj2 = __shfl_sync(FULL, c, j + 2);
            float cj3 = __shfl_sync(FULL, c, j + 3);
            int sj0 = __shfl_sync(FULL, s, j + 0);
            int sj1 = __shfl_sync(FULL, s, j + 1);
            int sj2 = __shfl_sync(FULL, s, j + 2);
            int sj3 = __shfl_sync(FULL, s, j + 3);
            float4 z0 = z4[sj0 * H4 + lane];
            float4 z1 = z4[sj1 * H4 + lane];
            float4 z2 = z4[sj2 * H4 + lane];
            float4 z3 = z4[sj3 * H4 + lane];
            acc.x += cj0 * z0.x; acc.y += cj0 * z0.y; acc.z += cj0 * z0.z; acc.w += cj0 * z0.w;
            acc.x += cj1 * z1.x; acc.y += cj1 * z1.y; acc.z += cj1 * z1.z; acc.w += cj1 * z1.w;
            acc.x += cj2 * z2.x; acc.y += cj2 * z2.y; acc.z += cj2 * z2.z; acc.w += cj2 * z2.w;
            acc.x += cj3 * z3.x; acc.y += cj3 * z3.y; acc.z += cj3 * z3.z; acc.w += cj3 * z3.w;
        }
        for (; j < cnt; j++) {
            float cj = __shfl_sync(FULL, c, j);
            int sj = __shfl_sync(FULL, s, j);
            float4 zs = z4[sj * H4 + lane];
            acc.x += cj * zs.x; acc.y += cj * zs.y;
            acc.z += cj * zs.z; acc.w += cj * zs.w;
        }
    }
    float4 b = __ldg(reinterpret_cast<const float4*>(b_gcn) + lane);
    float4 z = make_float4(fmaxf(acc.x + b.x, 0.f), fmaxf(acc.y + b.y, 0.f),
                           fmaxf(acc.z + b.z, 0.f), fmaxf(acc.w + b.w, 0.f));
    reinterpret_cast<float4*>(g_cur)[gw * H4 + lane] = z;
    float4* o4 = reinterpret_cast<float4*>(out) + gw * H4 + lane;
    float4 o = *o4;
    o.x = fmaxf(o.x, z.x); o.y = fmaxf(o.y, z.y);
    o.z = fmaxf(o.z, z.z); o.w = fmaxf(o.w, z.w);
    *o4 = o;
}

extern "C" void kernel_launch(void* const* d_in, const int* in_sizes, int n_in,
                              void* d_out, int out_size) {
    const float* x     = (const float*)d_in[0];
    const int*   ei    = (const int*)  d_in[1];
    const float* emask = (const float*)d_in[2];
    const float* W_gat = (const float*)d_in[3];
    const float* a_src = (const float*)d_in[4];
    const float* a_dst = (const float*)d_in[5];
    const float* b_gat = (const float*)d_in[6];
    const float* W_gcn = (const float*)d_in[7];
    const float* b_gcn = (const float*)d_in[8];
    float* out = (float*)d_out;

    const int nodeBlk  = (NN + 255) / 256;
    const int edgeBlk  = (NE + 255) / 256;
    const int gemmBlk  = ((NN / 8) * 32 + 255) / 256;   // 8 rows per warp
    const int nwarpBlk = (NN * 32 + 255) / 256;         // warp per node

    // CSR build (+ deg, dinv, GCN coefficients)
    k_zero<<<nodeBlk, 256>>>();
    k_hist<<<edgeBlk, 256>>>(ei, emask);
    k_scan<<<1, SCAN_T>>>();
    k_place<<<edgeBlk, 256>>>(ei, emask);

    // GAT
    k_gemm<true><<<gemmBlk, 256>>>(x, W_gat, a_src, a_dst);
    k_gat<<<nwarpBlk, 256>>>(b_gat, out);

    // 3x GCN + JK max
    for (int l = 0; l < 3; l++) {
        k_gemm<false><<<gemmBlk, 256>>>(nullptr, W_gcn + l * HID * HID, nullptr, nullptr);
        k_gcn<<<nwarpBlk, 256>>>(b_gcn + l * HID, out);
    }
}